// round 6
// baseline (speedup 1.0000x reference)
#include <cuda_runtime.h>

// Chamfer distance loss on (2,8,4096,3) fp32 clouds.
// Shared distance matrix (268M pairs): each pair updates the pred-side row-min
// and targ-side col-min. Min combining = atomicMax on inverted keys
// key = ~bits(max(d2,0)); identity 0 => statically zero-init buffer, reduce
// kernel re-zeroes slots after reading (stream-ordered for graph replay).
//
// Round-6: QUERY-packed f32x2 lanes (2 queries per packed op) so query state
// is 32 regs instead of 64 -> 3 blocks/SM (6 warps/SMSP) for issue efficiency.
// Targets live duplicated in smem float4s: (y0,y0,y1,y1) / (y2,y2,h,h).
// Per packed op: u = fma(m0,y0,fma(m1,y1,fma(m2,y2,x2))); w = u + h;
// row mins (per lane) + col min (across lanes) via scalar FMNMX.

#define NPTS    4096
#define NBATCH  16
#define THREADS 256
#define GRID    444                     // 3 blocks/SM x 148
#define TC      256                     // targets per chunk
#define QSTRIP  128                     // queries per strip (16 ty x 8)
#define NCHUNK  (NBATCH * 32 * 16)      // 8192 (32 strips x 16 tchunks / batch)
#define NQTOT   (2 * NBATCH * NPTS)     // 131072
#define BIGF    3.4e38f

#define P2_BLOCKS 128
#define P2_THREADS 256

typedef unsigned long long ull;

__device__ unsigned g_key[NQTOT];       // zero-init; [0:65536)=pred rows, rest=targ cols
__device__ float    g_sum;
__device__ unsigned g_done;

__device__ __forceinline__ ull pk(float lo, float hi) {
    ull r; asm("mov.b64 %0, {%1, %2};" : "=l"(r) : "f"(lo), "f"(hi)); return r;
}
__device__ __forceinline__ unsigned mkkey(float d2) {
    return ~__float_as_uint(fmaxf(d2, 0.0f));
}

__global__ void __launch_bounds__(THREADS, 3)
cd_main_kernel(const float* __restrict__ pred, const float* __restrict__ targ) {
    __shared__ __align__(16) float4 s4a[TC];   // (y0,y0,y1,y1) per target
    __shared__ __align__(16) float4 s4b[TC];   // (y2,y2, h, h) per target
    __shared__ unsigned scol[TC];

    const int tid = threadIdx.x;
    const int tx  = tid & 15;
    const int ty  = tid >> 4;
    const int bid = blockIdx.x;

    scol[tid] = 0u;                     // identity; published by first sync A

    const int c0 = (int)(((long long)bid       * NCHUNK) / GRID);
    const int c1 = (int)(((long long)(bid + 1) * NCHUNK) / GRID);

    ull  m0p[4], m1p[4], m2p[4], x2p[4];   // 2 queries per packed reg
    float r[8];                             // scalar row-min accumulators
    int cur_strip = -1, cur_qbase = 0;

    for (int cid = c0; cid < c1; cid++) {
        const int b  = cid >> 9;        // 512 chunks per batch (32 qs x 16 tc)
        const int rr = cid & 511;
        const int qs = rr >> 4;
        const int tc = rr & 15;

        // ---- query strip management: flush 8 row mins, load 8 new queries ----
        const int strip = (b << 5) | qs;
        if (strip != cur_strip) {
            if (cur_strip >= 0) {
#pragma unroll
                for (int i = 0; i < 8; i++)
                    atomicMax(&g_key[cur_qbase + (ty << 3) + i], mkkey(r[i]));
            }
            cur_strip = strip;
            cur_qbase = (b << 12) + (qs << 7);
            // 8 points = 24 floats = 6 x float4 (96B, 16B-aligned)
            const float4* __restrict__ qv =
                (const float4*)(pred + (size_t)(cur_qbase + (ty << 3)) * 3);
            float4 f[6];
#pragma unroll
            for (int i = 0; i < 6; i++) f[i] = qv[i];
            const float* q = (const float*)f;
#pragma unroll
            for (int p = 0; p < 4; p++) {
                const float a0 = q[(2 * p) * 3 + 0], b0 = q[(2 * p + 1) * 3 + 0];
                const float a1 = q[(2 * p) * 3 + 1], b1 = q[(2 * p + 1) * 3 + 1];
                const float a2 = q[(2 * p) * 3 + 2], b2 = q[(2 * p + 1) * 3 + 2];
                m0p[p] = pk(-2.0f * a0, -2.0f * b0);
                m1p[p] = pk(-2.0f * a1, -2.0f * b1);
                m2p[p] = pk(-2.0f * a2, -2.0f * b2);
                x2p[p] = pk(a0 * a0 + a1 * a1 + a2 * a2,
                            b0 * b0 + b1 * b1 + b2 * b2);
                r[2 * p] = BIGF; r[2 * p + 1] = BIGF;
            }
        }

        // ---- fill target tile: one target per thread, duplicated lanes ----
        {
            const float* __restrict__ bp =
                targ + (size_t)((b << 12) + (tc << 8) + tid) * 3;
            const float y0 = bp[0], y1 = bp[1], y2 = bp[2];
            const float h  = y0 * y0 + y1 * y1 + y2 * y2;
            s4a[tid] = make_float4(y0, y0, y1, y1);
            s4b[tid] = make_float4(y2, y2, h, h);
        }
        __syncthreads();    // A: tile + scol(identity) visible

        // ---- main: 16 targets x 4 query-pairs = 128 pairs/thread ----
#pragma unroll
        for (int k = 0; k < 16; k++) {
            const int j = tx + (k << 4);
            const float4 ua = s4a[j];     // LDS.128
            const float4 ub = s4b[j];     // LDS.128
            const ull y0d = pk(ua.x, ua.y);
            const ull y1d = pk(ua.z, ua.w);
            const ull y2d = pk(ub.x, ub.y);
            const ull hd  = pk(ub.z, ub.w);
            float ck = BIGF;
#pragma unroll
            for (int p = 0; p < 4; p++) {
                ull u, w;
                asm("fma.rn.f32x2 %0, %1, %2, %3;" : "=l"(u) : "l"(m2p[p]), "l"(y2d), "l"(x2p[p]));
                asm("fma.rn.f32x2 %0, %1, %2, %3;" : "=l"(u) : "l"(m1p[p]), "l"(y1d), "l"(u));
                asm("fma.rn.f32x2 %0, %1, %2, %3;" : "=l"(u) : "l"(m0p[p]), "l"(y0d), "l"(u));
                asm("add.rn.f32x2 %0, %1, %2;"     : "=l"(w) : "l"(u), "l"(hd));
                float wl, wh;
                asm("mov.b64 {%0, %1}, %2;" : "=f"(wl), "=f"(wh) : "l"(w));
                r[2 * p]     = fminf(r[2 * p],     wl);
                r[2 * p + 1] = fminf(r[2 * p + 1], wh);
                ck = fminf(ck, fminf(wl, wh));
            }
            // merge col partial across the paired ty groups, then smem atomic
            ck = fminf(ck, __shfl_xor_sync(0xFFFFFFFFu, ck, 16));
            if ((tid & 16) == 0)
                atomicMax(&scol[j], mkkey(ck));
        }
        __syncthreads();    // B: scol complete; tile reads done

        // ---- one global return-less atomicMax per target; reset own slot ----
        atomicMax(&g_key[(NBATCH * NPTS) + (b << 12) + (tc << 8) + tid], scol[tid]);
        scol[tid] = 0u;
    }

    // final row flush
    if (cur_strip >= 0) {
#pragma unroll
        for (int i = 0; i < 8; i++)
            atomicMax(&g_key[cur_qbase + (ty << 3) + i], mkkey(r[i]));
    }
}

// ---- pass 2: sqrt + mean; re-zeroes g_key (and g_sum/g_done) for next replay ----
__global__ void __launch_bounds__(P2_THREADS)
cd_reduce_kernel(float* __restrict__ out) {
    __shared__ float swsum[P2_THREADS / 32];
    const int tid = threadIdx.x;
    const int i = blockIdx.x * P2_THREADS + tid;     // 32768 threads, 1 uint4 each
    uint4* kp = reinterpret_cast<uint4*>(g_key);
    const uint4 kv = kp[i];
    float lsum = sqrtf(__uint_as_float(~kv.x)) + sqrtf(__uint_as_float(~kv.y))
               + sqrtf(__uint_as_float(~kv.z)) + sqrtf(__uint_as_float(~kv.w));
    kp[i] = make_uint4(0u, 0u, 0u, 0u);              // identity for next call
#pragma unroll
    for (int off = 16; off > 0; off >>= 1)
        lsum += __shfl_down_sync(0xFFFFFFFFu, lsum, off);
    const int lane = tid & 31;
    const int wid  = tid >> 5;
    if (lane == 0) swsum[wid] = lsum;
    __syncthreads();
    if (wid == 0) {
        float v = (lane < P2_THREADS / 32) ? swsum[lane] : 0.0f;
#pragma unroll
        for (int off = (P2_THREADS / 32) / 2; off > 0; off >>= 1)
            v += __shfl_down_sync(0xFFFFFFFFu, v, off);
        if (lane == 0) {
            atomicAdd(&g_sum, v);
            __threadfence();
            const unsigned rdone = atomicAdd(&g_done, 1u);
            if (rdone == P2_BLOCKS - 1) {
                out[0] = atomicAdd(&g_sum, 0.0f) * (1.0f / (float)(NBATCH * NPTS));
                g_sum = 0.0f;
                g_done = 0u;
            }
        }
    }
}

extern "C" void kernel_launch(void* const* d_in, const int* in_sizes, int n_in,
                              void* d_out, int out_size) {
    const float* pred = (const float*)d_in[0];
    const float* targ = (const float*)d_in[1];
    float* out = (float*)d_out;
    cd_main_kernel<<<GRID, THREADS>>>(pred, targ);
    cd_reduce_kernel<<<P2_BLOCKS, P2_THREADS>>>(out);
}

// round 8
// speedup vs baseline: 1.0844x; 1.0844x over previous
#include <cuda_runtime.h>

// Chamfer distance loss on (2,8,4096,3) fp32 clouds.
// Shared distance matrix (268M pairs): each pair updates the pred-side row-min
// and the targ-side col-min.  Min combining = atomicMax on inverted keys
// key = ~bits(max(d2,0)); identity 0 -> statically zero-init buffer; the
// reduce kernel re-zeroes slots after reading (stream-ordered for replay).
//
// Round-8: R3's minimal inner stream, Q=4 queries/thread (32 query regs)
// => ~79 regs => 3 blocks/SM (6 warps/SMSP) for issue-latency hiding.
// Per 2 targets x 1 query: s=add2(x2,h); w=fma2(m0,y0,fma2(m1,y1,fma2(m2,y2,s)));
// row/col mins via scalar FMNMX; all merges outside the hot loop.

#define NPTS    4096
#define NBATCH  16
#define THREADS 256
#define GRID    444                     // 3 blocks/SM x 148
#define TC      256                     // targets per chunk
#define QSTRIP  64                      // queries per strip (16 ty x 4)
#define NCHUNK  (NBATCH * 64 * 16)      // 16384 chunks (64 qstrips x 16 tchunks)
#define NQTOT   (2 * NBATCH * NPTS)     // 131072
#define BIGF    3.4e38f

#define P2_BLOCKS 128
#define P2_THREADS 256

typedef unsigned long long ull;

__device__ unsigned g_key[NQTOT];       // zero-init; [0:65536)=pred rows, rest=targ cols
__device__ float    g_sum;
__device__ unsigned g_done;

__device__ __forceinline__ ull dupf(float v) {
    ull r; asm("mov.b64 %0, {%1, %1};" : "=l"(r) : "f"(v)); return r;
}
__device__ __forceinline__ ull pk(float lo, float hi) {
    ull r; asm("mov.b64 %0, {%1, %2};" : "=l"(r) : "f"(lo), "f"(hi)); return r;
}
__device__ __forceinline__ unsigned mkkey(float d2) {
    return ~__float_as_uint(fmaxf(d2, 0.0f));
}

__global__ void __launch_bounds__(THREADS, 3)
cd_main_kernel(const float* __restrict__ pred, const float* __restrict__ targ) {
    __shared__ __align__(16) float4 sA[TC / 2];   // (y0_t0,y0_t1,y1_t0,y1_t1)
    __shared__ __align__(16) float4 sB[TC / 2];   // (y2_t0,y2_t1, h_t0, h_t1)
    __shared__ unsigned scol[TC];

    const int tid = threadIdx.x;
    const int tx  = tid & 15;
    const int ty  = tid >> 4;
    const int bid = blockIdx.x;

    scol[tid] = 0u;                     // identity; published by first sync A

    const int c0 = (int)(((long long)bid       * NCHUNK) / GRID);
    const int c1 = (int)(((long long)(bid + 1) * NCHUNK) / GRID);

    ull  m0[4], m1[4], m2[4], x2d[4];   // duplicated-lane query state (32 regs)
    float ralo[4], rahi[4];             // scalar row-min accumulators
    int cur_strip = -1, cur_qbase = 0;

    for (int cid = c0; cid < c1; cid++) {
        const int b  = cid >> 10;       // 1024 chunks per batch (64 qs x 16 tc)
        const int rr = cid & 1023;
        const int qs = rr >> 4;
        const int tc = rr & 15;

        // ---- query strip management: flush 4 row mins, load 4 new queries ----
        const int strip = (b << 6) | qs;
        if (strip != cur_strip) {
            if (cur_strip >= 0) {
#pragma unroll
                for (int i = 0; i < 4; i++)
                    atomicMax(&g_key[cur_qbase + (ty << 2) + i],
                              mkkey(fminf(ralo[i], rahi[i])));
            }
            cur_strip = strip;
            cur_qbase = (b << 12) + (qs << 6);
            // 4 points = 12 floats = 3 x float4 (48B, 16B-aligned)
            const float4* __restrict__ qv =
                (const float4*)(pred + (size_t)(cur_qbase + (ty << 2)) * 3);
            float4 f[3];
#pragma unroll
            for (int i = 0; i < 3; i++) f[i] = qv[i];
            const float* q = (const float*)f;
#pragma unroll
            for (int i = 0; i < 4; i++) {
                const float x0 = q[i * 3 + 0];
                const float x1 = q[i * 3 + 1];
                const float x2 = q[i * 3 + 2];
                m0[i]  = dupf(-2.0f * x0);
                m1[i]  = dupf(-2.0f * x1);
                m2[i]  = dupf(-2.0f * x2);
                x2d[i] = dupf(x0 * x0 + x1 * x1 + x2 * x2);
                ralo[i] = BIGF; rahi[i] = BIGF;
            }
        }

        // ---- fill target tile: 128 threads x 2 targets, interleaved float4 ----
        if (tid < 128) {
            const float* __restrict__ bp =
                targ + (size_t)((b << 12) + (tc << 8) + tid * 2) * 3;
            const float a0 = bp[0], a1 = bp[1], a2 = bp[2];
            const float b0 = bp[3], b1 = bp[4], b2 = bp[5];
            sA[tid] = make_float4(a0, b0, a1, b1);
            sB[tid] = make_float4(a2, b2,
                                  a0 * a0 + a1 * a1 + a2 * a2,
                                  b0 * b0 + b1 * b1 + b2 * b2);
        }
        float calo[8], cahi[8];
#pragma unroll
        for (int k = 0; k < 8; k++) { calo[k] = BIGF; cahi[k] = BIGF; }
        __syncthreads();    // A: tile + scol(identity) visible

        // ---- main: 8 target-pairs x 4 queries = 64 pairs/thread ----
#pragma unroll
        for (int k = 0; k < 8; k++) {
            const int pw = tx + (k << 4);
            const float4 ua = sA[pw];     // LDS.128
            const float4 ub = sB[pw];     // LDS.128
            const ull y0p = pk(ua.x, ua.y);
            const ull y1p = pk(ua.z, ua.w);
            const ull y2p = pk(ub.x, ub.y);
            const ull hp  = pk(ub.z, ub.w);
#pragma unroll
            for (int q = 0; q < 4; q++) {
                ull s, w;
                asm("add.rn.f32x2 %0, %1, %2;"     : "=l"(s) : "l"(x2d[q]), "l"(hp));
                asm("fma.rn.f32x2 %0, %1, %2, %3;" : "=l"(w) : "l"(m2[q]), "l"(y2p), "l"(s));
                asm("fma.rn.f32x2 %0, %1, %2, %3;" : "=l"(w) : "l"(m1[q]), "l"(y1p), "l"(w));
                asm("fma.rn.f32x2 %0, %1, %2, %3;" : "=l"(w) : "l"(m0[q]), "l"(y0p), "l"(w));
                float wl, wh;
                asm("mov.b64 {%0, %1}, %2;" : "=f"(wl), "=f"(wh) : "l"(w));
                ralo[q] = fminf(ralo[q], wl);
                rahi[q] = fminf(rahi[q], wh);
                calo[k] = fminf(calo[k], wl);
                cahi[k] = fminf(cahi[k], wh);
            }
        }

        // ---- col merge: direct smem atomics, outside the hot loop ----
#pragma unroll
        for (int k = 0; k < 8; k++) {
            const int w2 = (tx << 1) + (k << 5);
            atomicMax(&scol[w2],     mkkey(calo[k]));
            atomicMax(&scol[w2 + 1], mkkey(cahi[k]));
        }
        __syncthreads();    // B: scol complete; tile reads done

        // ---- one global return-less atomicMax per target; reset own slot ----
        atomicMax(&g_key[(NBATCH * NPTS) + (b << 12) + (tc << 8) + tid], scol[tid]);
        scol[tid] = 0u;
    }

    // final row flush
    if (cur_strip >= 0) {
#pragma unroll
        for (int i = 0; i < 4; i++)
            atomicMax(&g_key[cur_qbase + (ty << 2) + i],
                      mkkey(fminf(ralo[i], rahi[i])));
    }
}

// ---- pass 2: sqrt + mean; re-zeroes g_key (and g_sum/g_done) for next replay ----
__global__ void __launch_bounds__(P2_THREADS)
cd_reduce_kernel(float* __restrict__ out) {
    __shared__ float swsum[P2_THREADS / 32];
    const int tid = threadIdx.x;
    const int i = blockIdx.x * P2_THREADS + tid;     // 32768 threads, 1 uint4 each
    uint4* kp = reinterpret_cast<uint4*>(g_key);
    const uint4 kv = kp[i];
    float lsum = sqrtf(__uint_as_float(~kv.x)) + sqrtf(__uint_as_float(~kv.y))
               + sqrtf(__uint_as_float(~kv.z)) + sqrtf(__uint_as_float(~kv.w));
    kp[i] = make_uint4(0u, 0u, 0u, 0u);              // identity for next call
#pragma unroll
    for (int off = 16; off > 0; off >>= 1)
        lsum += __shfl_down_sync(0xFFFFFFFFu, lsum, off);
    const int lane = tid & 31;
    const int wid  = tid >> 5;
    if (lane == 0) swsum[wid] = lsum;
    __syncthreads();
    if (wid == 0) {
        float v = (lane < P2_THREADS / 32) ? swsum[lane] : 0.0f;
#pragma unroll
        for (int off = (P2_THREADS / 32) / 2; off > 0; off >>= 1)
            v += __shfl_down_sync(0xFFFFFFFFu, v, off);
        if (lane == 0) {
            atomicAdd(&g_sum, v);
            __threadfence();
            const unsigned rdone = atomicAdd(&g_done, 1u);
            if (rdone == P2_BLOCKS - 1) {
                out[0] = atomicAdd(&g_sum, 0.0f) * (1.0f / (float)(NBATCH * NPTS));
                g_sum = 0.0f;
                g_done = 0u;
            }
        }
    }
}

extern "C" void kernel_launch(void* const* d_in, const int* in_sizes, int n_in,
                              void* d_out, int out_size) {
    const float* pred = (const float*)d_in[0];
    const float* targ = (const float*)d_in[1];
    float* out = (float*)d_out;
    cd_main_kernel<<<GRID, THREADS>>>(pred, targ);
    cd_reduce_kernel<<<P2_BLOCKS, P2_THREADS>>>(out);
}

// round 9
// speedup vs baseline: 1.2017x; 1.1082x over previous
#include <cuda_runtime.h>

// Chamfer distance loss on (2,8,4096,3) fp32 clouds.
// Shared distance matrix (268M pairs): each pair updates the pred-side row-min
// and the targ-side col-min.  Min combining = atomicMax on inverted keys
// key = ~bits(max(d2,0)); identity 0 -> statically zero-init buffer; the
// reduce kernel re-zeroes slots after reading (stream-ordered for replay).
//
// Round-9: R3 structure, TC=512 (half the chunks -> half the barriers/fills),
// col atomics issued in-loop (return-less), 4 launches/call so ncu -s5 lands
// on the MAIN kernel (launch #6 = main of replay 2).

#define NPTS    4096
#define NBATCH  16
#define THREADS 256
#define GRID    296                     // 2 blocks/SM x 148
#define TC      512                     // targets per chunk
#define NCHUNK  (NBATCH * 32 * 8)       // 4096 chunks (32 qstrips x 8 tchunks)
#define NQTOT   (2 * NBATCH * NPTS)     // 131072
#define BIGF    3.4e38f

#define P2_BLOCKS 128
#define P2_THREADS 256

typedef unsigned long long ull;

__device__ unsigned g_key[NQTOT];       // zero-init; [0:65536)=pred rows, rest=targ cols
__device__ float    g_sum;
__device__ unsigned g_done;
__device__ unsigned g_tick;

__device__ __forceinline__ ull dupf(float v) {
    ull r; asm("mov.b64 %0, {%1, %1};" : "=l"(r) : "f"(v)); return r;
}
__device__ __forceinline__ ull pk(float lo, float hi) {
    ull r; asm("mov.b64 %0, {%1, %2};" : "=l"(r) : "f"(lo), "f"(hi)); return r;
}
__device__ __forceinline__ unsigned mkkey(float d2) {
    return ~__float_as_uint(fmaxf(d2, 0.0f));
}

// ---- launch 1: reset accumulators (also shifts ncu skip alignment) ----
__global__ void cd_reset_kernel() { g_sum = 0.0f; g_done = 0u; }

// ---- launch 4: tiny tail so each call contributes 4 launches ----
__global__ void cd_tail_kernel() { g_tick = 0u; }

// ---- launch 2: pairwise mins ----
__global__ void __launch_bounds__(THREADS, 2)
cd_main_kernel(const float* __restrict__ pred, const float* __restrict__ targ) {
    __shared__ __align__(16) float4 sA[TC / 2];   // (y0_t0,y0_t1,y1_t0,y1_t1)
    __shared__ __align__(16) float4 sB[TC / 2];   // (y2_t0,y2_t1, h_t0, h_t1)
    __shared__ unsigned scol[TC];

    const int tid = threadIdx.x;
    const int tx  = tid & 15;
    const int ty  = tid >> 4;
    const int bid = blockIdx.x;

    scol[tid] = 0u;                     // identity (both halves)
    scol[tid + 256] = 0u;

    const int c0 = (int)(((long long)bid       * NCHUNK) / GRID);
    const int c1 = (int)(((long long)(bid + 1) * NCHUNK) / GRID);

    ull  m0[8], m1[8], m2[8], x2d[8];   // duplicated-lane query state
    float ralo[8], rahi[8];             // row-min accumulators
    int cur_strip = -1, cur_qbase = 0;

    for (int cid = c0; cid < c1; cid++) {
        const int b  = cid >> 8;        // 256 chunks per batch (32 qs x 8 tc)
        const int rr = cid & 255;
        const int qs = rr >> 3;
        const int tc = rr & 7;

        // ---- query strip management: flush 8 row mins, load 8 new queries ----
        const int strip = (b << 5) | qs;
        if (strip != cur_strip) {
            if (cur_strip >= 0) {
#pragma unroll
                for (int i = 0; i < 8; i++)
                    atomicMax(&g_key[cur_qbase + (ty << 3) + i],
                              mkkey(fminf(ralo[i], rahi[i])));
            }
            cur_strip = strip;
            cur_qbase = (b << 12) + (qs << 7);
            // 8 points = 24 floats = 6 x float4 (96B, 16B-aligned)
            const float4* __restrict__ qv =
                (const float4*)(pred + (size_t)(cur_qbase + (ty << 3)) * 3);
            float4 f[6];
#pragma unroll
            for (int i = 0; i < 6; i++) f[i] = qv[i];
            const float* q = (const float*)f;
#pragma unroll
            for (int i = 0; i < 8; i++) {
                const float x0 = q[i * 3 + 0];
                const float x1 = q[i * 3 + 1];
                const float x2 = q[i * 3 + 2];
                m0[i]  = dupf(-2.0f * x0);
                m1[i]  = dupf(-2.0f * x1);
                m2[i]  = dupf(-2.0f * x2);
                x2d[i] = dupf(x0 * x0 + x1 * x1 + x2 * x2);
                ralo[i] = BIGF; rahi[i] = BIGF;
            }
        }

        // ---- fill target tile: 256 threads x 2 targets, interleaved float4 ----
        {
            const float* __restrict__ bp =
                targ + (size_t)((b << 12) + (tc << 9) + tid * 2) * 3;
            const float a0 = bp[0], a1 = bp[1], a2 = bp[2];
            const float b0 = bp[3], b1 = bp[4], b2 = bp[5];
            sA[tid] = make_float4(a0, b0, a1, b1);
            sB[tid] = make_float4(a2, b2,
                                  a0 * a0 + a1 * a1 + a2 * a2,
                                  b0 * b0 + b1 * b1 + b2 * b2);
        }
        __syncthreads();    // A: tile + scol(identity) visible

        // ---- main: 16 target-pairs x 8 queries = 256 pairs/thread ----
#pragma unroll
        for (int k = 0; k < 16; k++) {
            const int pw = tx + (k << 4);
            const float4 ua = sA[pw];     // LDS.128
            const float4 ub = sB[pw];     // LDS.128
            const ull y0p = pk(ua.x, ua.y);
            const ull y1p = pk(ua.z, ua.w);
            const ull y2p = pk(ub.x, ub.y);
            const ull hp  = pk(ub.z, ub.w);
            float clo = BIGF, chi = BIGF;
#pragma unroll
            for (int q = 0; q < 8; q++) {
                ull s, w;
                asm("add.rn.f32x2 %0, %1, %2;"     : "=l"(s) : "l"(x2d[q]), "l"(hp));
                asm("fma.rn.f32x2 %0, %1, %2, %3;" : "=l"(w) : "l"(m2[q]), "l"(y2p), "l"(s));
                asm("fma.rn.f32x2 %0, %1, %2, %3;" : "=l"(w) : "l"(m1[q]), "l"(y1p), "l"(w));
                asm("fma.rn.f32x2 %0, %1, %2, %3;" : "=l"(w) : "l"(m0[q]), "l"(y0p), "l"(w));
                float wl, wh;
                asm("mov.b64 {%0, %1}, %2;" : "=f"(wl), "=f"(wh) : "l"(w));
                ralo[q] = fminf(ralo[q], wl);
                rahi[q] = fminf(rahi[q], wh);
                clo = fminf(clo, wl);
                chi = fminf(chi, wh);
            }
            // in-loop, return-less col merges (no accumulator registers)
            const int w2 = (tx << 1) + (k << 5);
            atomicMax(&scol[w2],     mkkey(clo));
            atomicMax(&scol[w2 + 1], mkkey(chi));
        }
        __syncthreads();    // B: scol complete; tile reads done

        // ---- two global return-less atomicMax per thread; reset own slots ----
        const int gb = (NBATCH * NPTS) + (b << 12) + (tc << 9);
        atomicMax(&g_key[gb + tid],       scol[tid]);
        atomicMax(&g_key[gb + tid + 256], scol[tid + 256]);
        scol[tid] = 0u;
        scol[tid + 256] = 0u;
    }

    // final row flush
    if (cur_strip >= 0) {
#pragma unroll
        for (int i = 0; i < 8; i++)
            atomicMax(&g_key[cur_qbase + (ty << 3) + i],
                      mkkey(fminf(ralo[i], rahi[i])));
    }
}

// ---- launch 3: sqrt + mean; re-zeroes g_key for the next replay ----
__global__ void __launch_bounds__(P2_THREADS)
cd_reduce_kernel(float* __restrict__ out) {
    __shared__ float swsum[P2_THREADS / 32];
    const int tid = threadIdx.x;
    const int i = blockIdx.x * P2_THREADS + tid;     // 32768 threads, 1 uint4 each
    uint4* kp = reinterpret_cast<uint4*>(g_key);
    const uint4 kv = kp[i];
    float lsum = sqrtf(__uint_as_float(~kv.x)) + sqrtf(__uint_as_float(~kv.y))
               + sqrtf(__uint_as_float(~kv.z)) + sqrtf(__uint_as_float(~kv.w));
    kp[i] = make_uint4(0u, 0u, 0u, 0u);              // identity for next call
#pragma unroll
    for (int off = 16; off > 0; off >>= 1)
        lsum += __shfl_down_sync(0xFFFFFFFFu, lsum, off);
    const int lane = tid & 31;
    const int wid  = tid >> 5;
    if (lane == 0) swsum[wid] = lsum;
    __syncthreads();
    if (wid == 0) {
        float v = (lane < P2_THREADS / 32) ? swsum[lane] : 0.0f;
#pragma unroll
        for (int off = (P2_THREADS / 32) / 2; off > 0; off >>= 1)
            v += __shfl_down_sync(0xFFFFFFFFu, v, off);
        if (lane == 0) {
            atomicAdd(&g_sum, v);
            __threadfence();
            const unsigned rdone = atomicAdd(&g_done, 1u);
            if (rdone == P2_BLOCKS - 1)
                out[0] = atomicAdd(&g_sum, 0.0f) * (1.0f / (float)(NBATCH * NPTS));
        }
    }
}

extern "C" void kernel_launch(void* const* d_in, const int* in_sizes, int n_in,
                              void* d_out, int out_size) {
    const float* pred = (const float*)d_in[0];
    const float* targ = (const float*)d_in[1];
    float* out = (float*)d_out;
    cd_reset_kernel<<<1, 1>>>();                     // launch 1 (aligns ncu -s5 on main)
    cd_main_kernel<<<GRID, THREADS>>>(pred, targ);   // launch 2
    cd_reduce_kernel<<<P2_BLOCKS, P2_THREADS>>>(out);// launch 3
    cd_tail_kernel<<<1, 1>>>();                      // launch 4
}